// round 4
// baseline (speedup 1.0000x reference)
#include <cuda_runtime.h>
#include <cstdint>
#include <math.h>

// Qwen3.5 TopK Router — 3xTF32 mma.sync GEMM, raw-fp32 smem + consumer-side
// split, cp.async 3-stage pipeline, fused softmax/top-8/renorm.
// T=16384, D=2048, E=128, K=8.
// Grid: 128 CTAs x 256 threads. CTA tile 128 tokens x 128 experts.
// acc += Ahi*Bhi + Ahi*Blo + Alo*Bhi ; hi = cvt.rna.tf32(x), lo = x - hi
// (lo fed raw: HMMA truncates low mantissa bits -> error ~2^-23, negligible).

#define D_DIM  2048
#define E_EXP  128
#define TOPK   8
#define BM     128
#define KC     32
#define NCH    (D_DIM / KC)       // 64
#define NT     256
#define LPAD   129
#define STAGES 3

#define TILE_F  4096              // 128 rows x 32 cols (floats)
#define STAGE_F (2 * TILE_F)      // A raw + B raw
#define SMEM_B  (STAGES * STAGE_F * 4)   // 98304 bytes

static __device__ __forceinline__ float ftf32(float x) {
    uint32_t u;
    asm("cvt.rna.tf32.f32 %0, %1;" : "=r"(u) : "f"(x));
    return __uint_as_float(u);
}
static __device__ __forceinline__ uint32_t smem_u32(const void* p) {
    uint32_t a;
    asm("{ .reg .u64 t; cvta.to.shared.u64 t, %1; cvt.u32.u64 %0, t; }"
        : "=r"(a) : "l"(p));
    return a;
}
static __device__ __forceinline__ void cpasync16(uint32_t dst, const float* src) {
    asm volatile("cp.async.cg.shared.global [%0], [%1], 16;"
                 :: "r"(dst), "l"(src) : "memory");
}
static __device__ __forceinline__ void cp_commit() {
    asm volatile("cp.async.commit_group;" ::: "memory");
}
static __device__ __forceinline__ void cp_wait1() {
    asm volatile("cp.async.wait_group 1;" ::: "memory");
}

#define MMA_TF32(d, a0, a1, a2, a3, b0, b1)                                   \
    asm volatile(                                                             \
        "mma.sync.aligned.m16n8k8.row.col.f32.tf32.tf32.f32 "                 \
        "{%0,%1,%2,%3}, {%4,%5,%6,%7}, {%8,%9}, {%0,%1,%2,%3};"               \
        : "+f"((d)[0]), "+f"((d)[1]), "+f"((d)[2]), "+f"((d)[3])              \
        : "r"(__float_as_uint(a0)), "r"(__float_as_uint(a1)),                 \
          "r"(__float_as_uint(a2)), "r"(__float_as_uint(a3)),                 \
          "r"(__float_as_uint(b0)), "r"(__float_as_uint(b1)))

__global__ __launch_bounds__(NT, 1)
void router_mma(const float* __restrict__ X,
                const float* __restrict__ W,
                float* __restrict__ out, int T)
{
    extern __shared__ __align__(16) float smem[];
    __shared__ float smax[BM];
    __shared__ float srsum[BM];

    const uint32_t sbase = smem_u32(smem);
    const int tid  = threadIdx.x;
    const int wid  = tid >> 5;
    const int lane = tid & 31;
    const int row0 = blockIdx.x * BM;

    // -------- producer mapping (cp.async, 16B granules) --------
    // warp w loads rows 16w..16w+15 of A and B; q in 0..3:
    //   row = 16w + 4q + (lane>>3), col granule = (lane&7)*4
    const int psub = lane >> 3;
    const int pcol = (lane & 7) * 4;
    uint32_t adst[4];                  // stage-relative byte offsets (swizzled)
    const float* gA[4];
    const float* gB[4];
    #pragma unroll
    for (int q = 0; q < 4; q++) {
        const int r = 16 * wid + 4 * q + psub;
        adst[q] = (uint32_t)(r * 32 + (pcol ^ ((r & 7) << 2))) * 4u;
        gA[q] = X + (size_t)(row0 + r) * D_DIM + pcol;
        gB[q] = W + (size_t)r * D_DIM + pcol;
    }

    // -------- consumer mapping: warp grid 4(M) x 2(N), tile 32x64 --------
    const int g  = lane >> 2;
    const int tg = lane & 3;
    const int mrow0 = (wid & 3) * 32;
    const int ncol0 = (wid >> 2) * 64;
    const int cbase = tg ^ (g << 2);
    const int arow0 = (mrow0 + g) * 32;
    const int brow0 = (ncol0 + g) * 32;

    float acc[2][8][4];
    #pragma unroll
    for (int mt = 0; mt < 2; mt++)
        #pragma unroll
        for (int nt = 0; nt < 8; nt++)
            #pragma unroll
            for (int i = 0; i < 4; i++) acc[mt][nt][i] = 0.0f;

    // -------- pipeline prologue: issue chunks 0,1 --------
    #pragma unroll
    for (int c = 0; c < STAGES - 1; c++) {
        const uint32_t sA = sbase + c * (STAGE_F * 4);
        const uint32_t sB = sA + TILE_F * 4;
        #pragma unroll
        for (int q = 0; q < 4; q++) {
            cpasync16(sA + adst[q], gA[q] + c * KC);
            cpasync16(sB + adst[q], gB[q] + c * KC);
        }
        cp_commit();
    }

    // -------- main loop --------
    for (int c = 0; c < NCH; ++c) {
        cp_wait1();          // chunk c's copies (this thread's) complete
        __syncthreads();     // visibility + stage (c-1)%3 fully consumed

        // issue chunk c+2 into stage (c+2)%3 (just freed); always commit
        if (c + STAGES - 1 < NCH) {
            const int cn = c + STAGES - 1;
            const uint32_t sA = sbase + (cn % STAGES) * (STAGE_F * 4);
            const uint32_t sB = sA + TILE_F * 4;
            #pragma unroll
            for (int q = 0; q < 4; q++) {
                cpasync16(sA + adst[q], gA[q] + cn * KC);
                cpasync16(sB + adst[q], gB[q] + cn * KC);
            }
        }
        cp_commit();

        // compute on stage c%3
        const float* As = smem + (c % STAGES) * STAGE_F;
        const float* Bs = As + TILE_F;

        #pragma unroll
        for (int kb = 0; kb < 4; kb++) {
            const int c0 = cbase ^ (kb * 8);
            const int c1 = c0 ^ 4;

            float ah[2][4], al[2][4];
            #pragma unroll
            for (int mt = 0; mt < 2; mt++) {
                const int ro = arow0 + mt * 512;
                float r0 = As[ro + c0];
                float r1 = As[ro + 256 + c0];
                float r2 = As[ro + c1];
                float r3 = As[ro + 256 + c1];
                ah[mt][0] = ftf32(r0); al[mt][0] = r0 - ah[mt][0];
                ah[mt][1] = ftf32(r1); al[mt][1] = r1 - ah[mt][1];
                ah[mt][2] = ftf32(r2); al[mt][2] = r2 - ah[mt][2];
                ah[mt][3] = ftf32(r3); al[mt][3] = r3 - ah[mt][3];
            }
            float bh[8][2], bl[8][2];
            #pragma unroll
            for (int nt = 0; nt < 8; nt++) {
                const int ro = brow0 + nt * 256;
                float r0 = Bs[ro + c0];
                float r1 = Bs[ro + c1];
                bh[nt][0] = ftf32(r0); bl[nt][0] = r0 - bh[nt][0];
                bh[nt][1] = ftf32(r1); bl[nt][1] = r1 - bh[nt][1];
            }

            #pragma unroll
            for (int mt = 0; mt < 2; mt++)
                #pragma unroll
                for (int nt = 0; nt < 8; nt++)
                    MMA_TF32(acc[mt][nt], ah[mt][0], ah[mt][1], ah[mt][2], ah[mt][3],
                             bh[nt][0], bh[nt][1]);
            #pragma unroll
            for (int mt = 0; mt < 2; mt++)
                #pragma unroll
                for (int nt = 0; nt < 8; nt++)
                    MMA_TF32(acc[mt][nt], ah[mt][0], ah[mt][1], ah[mt][2], ah[mt][3],
                             bl[nt][0], bl[nt][1]);
            #pragma unroll
            for (int mt = 0; mt < 2; mt++)
                #pragma unroll
                for (int nt = 0; nt < 8; nt++)
                    MMA_TF32(acc[mt][nt], al[mt][0], al[mt][1], al[mt][2], al[mt][3],
                             bh[nt][0], bh[nt][1]);
        }
    }
    __syncthreads();   // all stages consumed; smem free for epilogue

    // -------- epilogue: accum -> smem logits tile --------
    float* Ls = smem;  // [BM][LPAD] = 66048 B < 98304 B
    #pragma unroll
    for (int mt = 0; mt < 2; mt++) {
        #pragma unroll
        for (int nt = 0; nt < 8; nt++) {
            const int r_ = mrow0 + mt * 16 + g;
            const int c_ = ncol0 + nt * 8 + tg * 2;
            Ls[r_ * LPAD + c_]           = acc[mt][nt][0];
            Ls[r_ * LPAD + c_ + 1]       = acc[mt][nt][1];
            Ls[(r_ + 8) * LPAD + c_]     = acc[mt][nt][2];
            Ls[(r_ + 8) * LPAD + c_ + 1] = acc[mt][nt][3];
        }
    }
    __syncthreads();

    // per-token max & exp-sum
    if (tid < BM) {
        const float* r = Ls + tid * LPAD;
        float m = r[0];
        #pragma unroll 4
        for (int e = 1; e < E_EXP; e++) m = fmaxf(m, r[e]);
        float s = 0.0f;
        #pragma unroll 4
        for (int e = 0; e < E_EXP; e++) s += __expf(r[e] - m);
        smax[tid]  = m;
        srsum[tid] = 1.0f / s;
    }
    __syncthreads();

    // softmax probs -> smem overwrite + coalesced logits write
    for (int i = tid; i < BM * E_EXP; i += NT) {
        const int t = i >> 7;
        const int e = i & 127;
        const float p = __expf(Ls[t * LPAD + e] - smax[t]) * srsum[t];
        Ls[t * LPAD + e] = p;
        out[(size_t)(row0 + t) * E_EXP + e] = p;
    }
    __syncthreads();

    // top-8 (strict > keeps lowest index on ties) + renormalize
    if (tid < BM) {
        float* r = Ls + tid * LPAD;
        float vals[TOPK];
        int   idxs[TOPK];
        float s = 0.0f;
        #pragma unroll
        for (int k = 0; k < TOPK; k++) {
            float bv = -1.0f;
            int   bi = 0;
            for (int e = 0; e < E_EXP; e++) {
                float v = r[e];
                if (v > bv) { bv = v; bi = e; }
            }
            r[bi]   = -1.0f;
            vals[k] = bv;
            idxs[k] = bi;
            s += bv;
        }
        const float rs = 1.0f / s;
        const size_t bw = (size_t)T * E_EXP + (size_t)(row0 + tid) * TOPK;
        const size_t bx = (size_t)T * E_EXP + (size_t)T * TOPK + (size_t)(row0 + tid) * TOPK;
        #pragma unroll
        for (int k = 0; k < TOPK; k++) {
            out[bw + k] = vals[k] * rs;
            out[bx + k] = (float)idxs[k];
        }
    }
}

extern "C" void kernel_launch(void* const* d_in, const int* in_sizes, int n_in,
                              void* d_out, int out_size)
{
    const float* X = (const float*)d_in[0];   // hidden_states [T, 2048]
    const float* W = (const float*)d_in[1];   // weight        [128, 2048]
    float* out = (float*)d_out;

    const int T = in_sizes[0] / D_DIM;        // 16384
    static int configured = -1;
    if (configured < 0) {
        cudaFuncSetAttribute(router_mma,
                             cudaFuncAttributeMaxDynamicSharedMemorySize, SMEM_B);
        configured = 1;
    }
    router_mma<<<T / BM, NT, SMEM_B>>>(X, W, out, T);
}

// round 5
// speedup vs baseline: 1.6105x; 1.6105x over previous
#include <cuda_runtime.h>
#include <cuda_fp16.h>
#include <cstdint>
#include <math.h>

// Qwen3.5 TopK Router — 3-pass FP16-split mma.sync(m16n8k16) GEMM + fused
// softmax/top-8/renorm.
// tf32 m16n8k8 saturated at 50% of the HMMA pipe (half-rate dtype). fp16
// m16n8k16 does 2x the K per instruction at the same issue rate.
// Accuracy: x' = x*Sx, w' = w*Sw (powers of 2); hi = f16_rn(x'), lo = x'-hi.
// acc += Ah*Bh + Ah*Bl + Al*Bh ; logits = acc * 1/(Sx*Sw).
// Residual ~2^-22 (same as tf32 3-pass). Scaling keeps lo out of subnormals.
//
// Output layout (float32): [T*E logits][T*K weights][T*K indices-as-float]

#define D_DIM  2048
#define E_EXP  128
#define TOPK   8
#define BM     128
#define KC     32                 // fp32 K elems per chunk
#define NCH    (D_DIM / KC)       // 64
#define NT     256
#define LPAD   129

#define SX      1024.0f
#define SW      64.0f
#define RESCALE (1.0f / 65536.0f)

// tile: [128 rows][16 b32 half2-words] = 8192 B; 4 tiles/stage, 2 stages
#define TILE_W   16
#define TILE_U   (BM * TILE_W)    // b32 words per tile = 2048
#define STAGE_U  (4 * TILE_U)     // Ahi|Alo|Bhi|Blo = 8192 words = 32 KB
#define SMEM_B   66560            // max(2*32KB, 128*129*4 epilogue) rounded

#define MMA_F16(d, a0, a1, a2, a3, b0, b1)                                    \
    asm volatile(                                                             \
        "mma.sync.aligned.m16n8k16.row.col.f32.f16.f16.f32 "                  \
        "{%0,%1,%2,%3}, {%4,%5,%6,%7}, {%8,%9}, {%0,%1,%2,%3};"               \
        : "+f"((d)[0]), "+f"((d)[1]), "+f"((d)[2]), "+f"((d)[3])              \
        : "r"(a0), "r"(a1), "r"(a2), "r"(a3), "r"(b0), "r"(b1))

// split one fp32 pair (k-even, k-odd) into packed hi/lo half2
static __device__ __forceinline__ void split2(float x0, float x1,
                                              uint32_t& hi, uint32_t& lo) {
    half2 h = __floats2half2_rn(x0, x1);
    float2 hf = __half22float2(h);
    half2 l = __floats2half2_rn(x0 - hf.x, x1 - hf.y);
    hi = *(uint32_t*)&h;
    lo = *(uint32_t*)&l;
}

__global__ __launch_bounds__(NT, 1)
void router_mma(const float* __restrict__ X,
                const float* __restrict__ W,
                float* __restrict__ out, int T)
{
    extern __shared__ __align__(16) uint32_t smem[];
    __shared__ float smax[BM];
    __shared__ float srsum[BM];

    const int tid  = threadIdx.x;
    const int wid  = tid >> 5;
    const int lane = tid & 31;
    const int row0 = blockIdx.x * BM;

    // -------- producer mapping --------
    // warp w loads rows 16w..16w+15; q 0..3: row=16w+4q+(lane>>3),
    // fp32 cols (lane&7)*4 .. +3  (coalesced float4)
    const int psub = lane >> 3;
    const int pcol = (lane & 7) * 4;           // fp32 col
    const int pw   = pcol >> 1;                // half2 word (even)
    const float* gA[4];
    const float* gB[4];
    int sidx[4];                               // swizzled word index in tile
    #pragma unroll
    for (int q = 0; q < 4; q++) {
        const int r = 16 * wid + 4 * q + psub;
        gA[q] = X + (size_t)(row0 + r) * D_DIM + pcol;
        gB[q] = W + (size_t)r * D_DIM + pcol;
        sidx[q] = r * TILE_W + (pw ^ ((r & 6) << 1));
    }

    // -------- consumer mapping: warp grid 4(M) x 2(N), tile 32x64 --------
    const int g  = lane >> 2;
    const int tg = lane & 3;
    const int mrow0 = (wid & 3) * 32;
    const int ncol0 = (wid >> 2) * 64;

    float acc[2][8][4];
    #pragma unroll
    for (int mt = 0; mt < 2; mt++)
        #pragma unroll
        for (int nt = 0; nt < 8; nt++)
            #pragma unroll
            for (int i = 0; i < 4; i++) acc[mt][nt][i] = 0.0f;

    float4 ra[4], rb[4];

    // ---- prologue: chunk 0 -> stage 0 ----
    #pragma unroll
    for (int q = 0; q < 4; q++) {
        ra[q] = *(const float4*)gA[q];
        rb[q] = *(const float4*)gB[q];
    }
    {
        uint32_t* Ah = smem;              uint32_t* Al = smem + TILE_U;
        uint32_t* Bh = smem + 2*TILE_U;   uint32_t* Bl = smem + 3*TILE_U;
        #pragma unroll
        for (int q = 0; q < 4; q++) {
            uint32_t h0, l0, h1, l1;
            split2(ra[q].x * SX, ra[q].y * SX, h0, l0);
            split2(ra[q].z * SX, ra[q].w * SX, h1, l1);
            Ah[sidx[q]] = h0; Ah[sidx[q] + 1] = h1;
            Al[sidx[q]] = l0; Al[sidx[q] + 1] = l1;
            split2(rb[q].x * SW, rb[q].y * SW, h0, l0);
            split2(rb[q].z * SW, rb[q].w * SW, h1, l1);
            Bh[sidx[q]] = h0; Bh[sidx[q] + 1] = h1;
            Bl[sidx[q]] = l0; Bl[sidx[q] + 1] = l1;
        }
    }
    __syncthreads();

    // ---- main loop ----
    for (int c = 0; c < NCH; ++c) {
        if (c + 1 < NCH) {
            const int ko = (c + 1) * KC;
            #pragma unroll
            for (int q = 0; q < 4; q++) {
                ra[q] = *(const float4*)(gA[q] + ko);
                rb[q] = *(const float4*)(gB[q] + ko);
            }
        }

        // compute on stage c&1
        {
            const uint32_t* Ah = smem + (c & 1) * STAGE_U;
            const uint32_t* Al = Ah + TILE_U;
            const uint32_t* Bh = Ah + 2 * TILE_U;
            const uint32_t* Bl = Ah + 3 * TILE_U;

            #pragma unroll
            for (int kb = 0; kb < 2; kb++) {     // two k16 blocks per chunk
                uint32_t ah[2][4], al[2][4];
                #pragma unroll
                for (int mt = 0; mt < 2; mt++) {
                    const int r0_ = mrow0 + mt * 16 + g;
                    const int r1_ = r0_ + 8;
                    const int w00 = kb * 8 + tg;
                    const int i00 = r0_ * TILE_W + (w00       ^ ((r0_ & 6) << 1));
                    const int i01 = r0_ * TILE_W + ((w00 + 4) ^ ((r0_ & 6) << 1));
                    const int i10 = r1_ * TILE_W + (w00       ^ ((r1_ & 6) << 1));
                    const int i11 = r1_ * TILE_W + ((w00 + 4) ^ ((r1_ & 6) << 1));
                    ah[mt][0] = Ah[i00]; ah[mt][1] = Ah[i10];
                    ah[mt][2] = Ah[i01]; ah[mt][3] = Ah[i11];
                    al[mt][0] = Al[i00]; al[mt][1] = Al[i10];
                    al[mt][2] = Al[i01]; al[mt][3] = Al[i11];
                }
                uint32_t bh[8][2], bl[8][2];
                #pragma unroll
                for (int nt = 0; nt < 8; nt++) {
                    const int r_ = ncol0 + nt * 8 + g;
                    const int w0 = kb * 8 + tg;
                    const int i0 = r_ * TILE_W + (w0       ^ ((r_ & 6) << 1));
                    const int i1 = r_ * TILE_W + ((w0 + 4) ^ ((r_ & 6) << 1));
                    bh[nt][0] = Bh[i0]; bh[nt][1] = Bh[i1];
                    bl[nt][0] = Bl[i0]; bl[nt][1] = Bl[i1];
                }

                #pragma unroll
                for (int mt = 0; mt < 2; mt++)
                    #pragma unroll
                    for (int nt = 0; nt < 8; nt++)
                        MMA_F16(acc[mt][nt], ah[mt][0], ah[mt][1], ah[mt][2], ah[mt][3],
                                bh[nt][0], bh[nt][1]);
                #pragma unroll
                for (int mt = 0; mt < 2; mt++)
                    #pragma unroll
                    for (int nt = 0; nt < 8; nt++)
                        MMA_F16(acc[mt][nt], ah[mt][0], ah[mt][1], ah[mt][2], ah[mt][3],
                                bl[nt][0], bl[nt][1]);
                #pragma unroll
                for (int mt = 0; mt < 2; mt++)
                    #pragma unroll
                    for (int nt = 0; nt < 8; nt++)
                        MMA_F16(acc[mt][nt], al[mt][0], al[mt][1], al[mt][2], al[mt][3],
                                bh[nt][0], bh[nt][1]);
            }
        }

        // convert + commit next chunk into other stage
        if (c + 1 < NCH) {
            uint32_t* Ah = smem + ((c + 1) & 1) * STAGE_U;
            uint32_t* Al = Ah + TILE_U;
            uint32_t* Bh = Ah + 2 * TILE_U;
            uint32_t* Bl = Ah + 3 * TILE_U;
            #pragma unroll
            for (int q = 0; q < 4; q++) {
                uint32_t h0, l0, h1, l1;
                split2(ra[q].x * SX, ra[q].y * SX, h0, l0);
                split2(ra[q].z * SX, ra[q].w * SX, h1, l1);
                Ah[sidx[q]] = h0; Ah[sidx[q] + 1] = h1;
                Al[sidx[q]] = l0; Al[sidx[q] + 1] = l1;
                split2(rb[q].x * SW, rb[q].y * SW, h0, l0);
                split2(rb[q].z * SW, rb[q].w * SW, h1, l1);
                Bh[sidx[q]] = h0; Bh[sidx[q] + 1] = h1;
                Bl[sidx[q]] = l0; Bl[sidx[q] + 1] = l1;
            }
        }
        __syncthreads();
    }

    // ---- epilogue: rescale accum -> smem logits tile ----
    float* Ls = (float*)smem;   // [BM][LPAD]
    #pragma unroll
    for (int mt = 0; mt < 2; mt++) {
        #pragma unroll
        for (int nt = 0; nt < 8; nt++) {
            const int r_ = mrow0 + mt * 16 + g;
            const int c_ = ncol0 + nt * 8 + tg * 2;
            Ls[r_ * LPAD + c_]           = acc[mt][nt][0] * RESCALE;
            Ls[r_ * LPAD + c_ + 1]       = acc[mt][nt][1] * RESCALE;
            Ls[(r_ + 8) * LPAD + c_]     = acc[mt][nt][2] * RESCALE;
            Ls[(r_ + 8) * LPAD + c_ + 1] = acc[mt][nt][3] * RESCALE;
        }
    }
    __syncthreads();

    // per-token max & exp-sum
    if (tid < BM) {
        const float* r = Ls + tid * LPAD;
        float m = r[0];
        #pragma unroll 4
        for (int e = 1; e < E_EXP; e++) m = fmaxf(m, r[e]);
        float s = 0.0f;
        #pragma unroll 4
        for (int e = 0; e < E_EXP; e++) s += __expf(r[e] - m);
        smax[tid]  = m;
        srsum[tid] = 1.0f / s;
    }
    __syncthreads();

    // softmax probs -> smem overwrite + coalesced logits write
    for (int i = tid; i < BM * E_EXP; i += NT) {
        const int t = i >> 7;
        const int e = i & 127;
        const float p = __expf(Ls[t * LPAD + e] - smax[t]) * srsum[t];
        Ls[t * LPAD + e] = p;
        out[(size_t)(row0 + t) * E_EXP + e] = p;
    }
    __syncthreads();

    // top-8 (strict > keeps lowest index on ties) + renormalize
    if (tid < BM) {
        float* r = Ls + tid * LPAD;
        float vals[TOPK];
        int   idxs[TOPK];
        float s = 0.0f;
        #pragma unroll
        for (int k = 0; k < TOPK; k++) {
            float bv = -1.0f;
            int   bi = 0;
            for (int e = 0; e < E_EXP; e++) {
                float v = r[e];
                if (v > bv) { bv = v; bi = e; }
            }
            r[bi]   = -1.0f;
            vals[k] = bv;
            idxs[k] = bi;
            s += bv;
        }
        const float rs = 1.0f / s;
        const size_t bw = (size_t)T * E_EXP + (size_t)(row0 + tid) * TOPK;
        const size_t bx = (size_t)T * E_EXP + (size_t)T * TOPK + (size_t)(row0 + tid) * TOPK;
        #pragma unroll
        for (int k = 0; k < TOPK; k++) {
            out[bw + k] = vals[k] * rs;
            out[bx + k] = (float)idxs[k];
        }
    }
}

extern "C" void kernel_launch(void* const* d_in, const int* in_sizes, int n_in,
                              void* d_out, int out_size)
{
    const float* X = (const float*)d_in[0];   // hidden_states [T, 2048]
    const float* W = (const float*)d_in[1];   // weight        [128, 2048]
    float* out = (float*)d_out;

    const int T = in_sizes[0] / D_DIM;        // 16384
    static int configured = -1;
    if (configured < 0) {
        cudaFuncSetAttribute(router_mma,
                             cudaFuncAttributeMaxDynamicSharedMemorySize, SMEM_B);
        configured = 1;
    }
    router_mma<<<T / BM, NT, SMEM_B>>>(X, W, out, T);
}

// round 6
// speedup vs baseline: 1.7175x; 1.0664x over previous
#include <cuda_runtime.h>
#include <cuda_fp16.h>
#include <cstdint>
#include <math.h>

// Qwen3.5 TopK Router — 3-pass FP16-split mma.sync(m16n8k16) + ldmatrix,
// 16 warps/CTA for latency hiding, fused softmax/top-8/renorm.
// x' = x*1024, w' = w*64 (powers of 2; keeps lo out of fp16 subnormals);
// hi = f16_rn(v), lo = f16_rn(v - hi); acc += Ah*Bh + Ah*Bl + Al*Bh;
// logits = acc / 65536.  Residual ~2^-22 == fp32-grade.
//
// Output (float32): [T*E logits][T*K weights][T*K indices-as-float]

#define D_DIM  2048
#define E_EXP  128
#define TOPK   8
#define BM     128
#define KC     32                 // fp32 K per chunk
#define NCH    (D_DIM / KC)       // 64
#define NT     512
#define LPAD   129

#define SX      1024.0f
#define SW      64.0f
#define RESCALE (1.0f / 65536.0f)

// tile: 128 rows x 64B (32 halves) = 8192 B. Ah|Al|Bh|Bl per stage, 2 stages.
#define TILE_B   8192
#define STAGE_B  (4 * TILE_B)     // 32768
#define SMEM_B   66560            // >= max(2*STAGE_B, 128*129*4)

#define MMA_F16(d, a0, a1, a2, a3, b0, b1)                                    \
    asm volatile(                                                             \
        "mma.sync.aligned.m16n8k16.row.col.f32.f16.f16.f32 "                  \
        "{%0,%1,%2,%3}, {%4,%5,%6,%7}, {%8,%9}, {%0,%1,%2,%3};"               \
        : "+f"((d)[0]), "+f"((d)[1]), "+f"((d)[2]), "+f"((d)[3])              \
        : "r"(a0), "r"(a1), "r"(a2), "r"(a3), "r"(b0), "r"(b1))

#define LDSM_X4(r, addr)                                                      \
    asm volatile(                                                             \
        "ldmatrix.sync.aligned.m8n8.x4.shared.b16 {%0,%1,%2,%3}, [%4];"       \
        : "=r"((r)[0]), "=r"((r)[1]), "=r"((r)[2]), "=r"((r)[3])              \
        : "r"(addr))

static __device__ __forceinline__ uint32_t smem_u32(const void* p) {
    uint32_t a;
    asm("{ .reg .u64 t; cvta.to.shared.u64 t, %1; cvt.u32.u64 %0, t; }"
        : "=r"(a) : "l"(p));
    return a;
}
// split fp32 pair into packed hi/lo half2
static __device__ __forceinline__ void split2(float x0, float x1,
                                              uint32_t& hi, uint32_t& lo) {
    half2 h = __floats2half2_rn(x0, x1);
    float2 hf = __half22float2(h);
    half2 l = __floats2half2_rn(x0 - hf.x, x1 - hf.y);
    hi = *(uint32_t*)&h;
    lo = *(uint32_t*)&l;
}

__global__ __launch_bounds__(NT, 1)
void router_mma(const float* __restrict__ X,
                const float* __restrict__ W,
                float* __restrict__ out, int T)
{
    extern __shared__ __align__(16) uint32_t smem[];
    __shared__ float smax[BM];
    __shared__ float srsum[BM];

    const uint32_t sbase = smem_u32(smem);
    const int tid  = threadIdx.x;
    const int wid  = tid >> 5;
    const int lane = tid & 31;
    const int row0 = blockIdx.x * BM;

    // -------- producer mapping (16 warps) --------
    // warp w loads A rows 8w..8w+7 and B rows 8w..8w+7.
    // q in 0..1: row = 8w + 4q + (lane>>3); fp32 cols (lane&7)*4..+3
    const int psub = lane >> 3;
    const int pcol = (lane & 7) * 4;           // fp32 col
    const float* gA[2];
    const float* gB[2];
    uint32_t soff[2];                           // byte offset within a tile
    #pragma unroll
    for (int q = 0; q < 2; q++) {
        const int r = 8 * wid + 4 * q + psub;
        gA[q] = X + (size_t)(row0 + r) * D_DIM + pcol;
        gB[q] = W + (size_t)r * D_DIM + pcol;
        const int g   = (lane & 7) >> 1;        // 16B granule 0..3
        const int sub = (lane & 1) * 8;         // byte offset inside granule
        soff[q] = (uint32_t)(r * 64 + ((g ^ ((r >> 1) & 3)) << 4) + sub);
    }

    // -------- consumer mapping: warp grid 4(M) x 4(N), tile 32x32 --------
    const int g_  = lane >> 2;
    const int tg  = lane & 3;
    const int mrow0 = (wid & 3) * 32;
    const int ncol0 = (wid >> 2) * 32;

    // ldmatrix per-lane byte offsets (within a tile)
    uint32_t offA[2][2], offB[2][2];            // [mt or p][kb]
    {
        const int rA = (lane & 7) + ((lane >> 3) & 1) * 8;
        const int gsA = lane >> 4;
        #pragma unroll
        for (int mt = 0; mt < 2; mt++) {
            const int row = mrow0 + mt * 16 + rA;
            const int sw  = (row >> 1) & 3;
            #pragma unroll
            for (int kb = 0; kb < 2; kb++)
                offA[mt][kb] = (uint32_t)(row * 64 + (((kb * 2 + gsA) ^ sw) << 4));
        }
        const int rB = (lane & 7) + ((lane >> 4) << 3);
        const int gsB = (lane >> 3) & 1;
        #pragma unroll
        for (int p = 0; p < 2; p++) {
            const int row = ncol0 + p * 16 + rB;
            const int sw  = (row >> 1) & 3;
            #pragma unroll
            for (int kb = 0; kb < 2; kb++)
                offB[p][kb] = (uint32_t)(row * 64 + (((kb * 2 + gsB) ^ sw) << 4));
        }
    }

    float acc[2][4][4];
    #pragma unroll
    for (int mt = 0; mt < 2; mt++)
        #pragma unroll
        for (int nt = 0; nt < 4; nt++)
            #pragma unroll
            for (int i = 0; i < 4; i++) acc[mt][nt][i] = 0.0f;

    float4 ra[2], rb[2];

    // ---- prologue: chunk 0 -> stage 0 ----
    #pragma unroll
    for (int q = 0; q < 2; q++) {
        ra[q] = *(const float4*)gA[q];
        rb[q] = *(const float4*)gB[q];
    }
    #pragma unroll
    for (int q = 0; q < 2; q++) {
        uint32_t h0, l0, h1, l1;
        split2(ra[q].x * SX, ra[q].y * SX, h0, l0);
        split2(ra[q].z * SX, ra[q].w * SX, h1, l1);
        *(uint2*)((char*)smem + soff[q])              = make_uint2(h0, h1);
        *(uint2*)((char*)smem + TILE_B + soff[q])     = make_uint2(l0, l1);
        split2(rb[q].x * SW, rb[q].y * SW, h0, l0);
        split2(rb[q].z * SW, rb[q].w * SW, h1, l1);
        *(uint2*)((char*)smem + 2 * TILE_B + soff[q]) = make_uint2(h0, h1);
        *(uint2*)((char*)smem + 3 * TILE_B + soff[q]) = make_uint2(l0, l1);
    }
    __syncthreads();

    // ---- main loop ----
    for (int c = 0; c < NCH; ++c) {
        if (c + 1 < NCH) {
            const int ko = (c + 1) * KC;
            #pragma unroll
            for (int q = 0; q < 2; q++) {
                ra[q] = *(const float4*)(gA[q] + ko);
                rb[q] = *(const float4*)(gB[q] + ko);
            }
        }

        const uint32_t stg = sbase + (uint32_t)(c & 1) * STAGE_B;

        #pragma unroll
        for (int kb = 0; kb < 2; kb++) {
            uint32_t ah[2][4], al[2][4], bh[2][4], bl[2][4];
            #pragma unroll
            for (int mt = 0; mt < 2; mt++) {
                LDSM_X4(ah[mt], stg + offA[mt][kb]);
                LDSM_X4(al[mt], stg + TILE_B + offA[mt][kb]);
            }
            #pragma unroll
            for (int p = 0; p < 2; p++) {
                LDSM_X4(bh[p], stg + 2 * TILE_B + offB[p][kb]);
                LDSM_X4(bl[p], stg + 3 * TILE_B + offB[p][kb]);
            }
            // nt -> (p = nt>>1, half = nt&1): regs (0,1) or (2,3)
            #pragma unroll
            for (int mt = 0; mt < 2; mt++)
                #pragma unroll
                for (int nt = 0; nt < 4; nt++) {
                    const int p = nt >> 1, h = (nt & 1) * 2;
                    MMA_F16(acc[mt][nt], ah[mt][0], ah[mt][1], ah[mt][2], ah[mt][3],
                            bh[p][h], bh[p][h + 1]);
                }
            #pragma unroll
            for (int mt = 0; mt < 2; mt++)
                #pragma unroll
                for (int nt = 0; nt < 4; nt++) {
                    const int p = nt >> 1, h = (nt & 1) * 2;
                    MMA_F16(acc[mt][nt], ah[mt][0], ah[mt][1], ah[mt][2], ah[mt][3],
                            bl[p][h], bl[p][h + 1]);
                }
            #pragma unroll
            for (int mt = 0; mt < 2; mt++)
                #pragma unroll
                for (int nt = 0; nt < 4; nt++) {
                    const int p = nt >> 1, h = (nt & 1) * 2;
                    MMA_F16(acc[mt][nt], al[mt][0], al[mt][1], al[mt][2], al[mt][3],
                            bh[p][h], bh[p][h + 1]);
                }
        }

        if (c + 1 < NCH) {
            char* stn = (char*)smem + ((c + 1) & 1) * STAGE_B;
            #pragma unroll
            for (int q = 0; q < 2; q++) {
                uint32_t h0, l0, h1, l1;
                split2(ra[q].x * SX, ra[q].y * SX, h0, l0);
                split2(ra[q].z * SX, ra[q].w * SX, h1, l1);
                *(uint2*)(stn + soff[q])              = make_uint2(h0, h1);
                *(uint2*)(stn + TILE_B + soff[q])     = make_uint2(l0, l1);
                split2(rb[q].x * SW, rb[q].y * SW, h0, l0);
                split2(rb[q].z * SW, rb[q].w * SW, h1, l1);
                *(uint2*)(stn + 2 * TILE_B + soff[q]) = make_uint2(h0, h1);
                *(uint2*)(stn + 3 * TILE_B + soff[q]) = make_uint2(l0, l1);
            }
        }
        __syncthreads();
    }

    // ---- epilogue: rescale accum -> smem logits tile ----
    float* Ls = (float*)smem;   // [BM][LPAD]
    #pragma unroll
    for (int mt = 0; mt < 2; mt++) {
        #pragma unroll
        for (int nt = 0; nt < 4; nt++) {
            const int r_ = mrow0 + mt * 16 + g_;
            const int c_ = ncol0 + nt * 8 + tg * 2;
            Ls[r_ * LPAD + c_]           = acc[mt][nt][0] * RESCALE;
            Ls[r_ * LPAD + c_ + 1]       = acc[mt][nt][1] * RESCALE;
            Ls[(r_ + 8) * LPAD + c_]     = acc[mt][nt][2] * RESCALE;
            Ls[(r_ + 8) * LPAD + c_ + 1] = acc[mt][nt][3] * RESCALE;
        }
    }
    __syncthreads();

    // per-token max & exp-sum
    if (tid < BM) {
        const float* r = Ls + tid * LPAD;
        float m = r[0];
        #pragma unroll 4
        for (int e = 1; e < E_EXP; e++) m = fmaxf(m, r[e]);
        float s = 0.0f;
        #pragma unroll 4
        for (int e = 0; e < E_EXP; e++) s += __expf(r[e] - m);
        smax[tid]  = m;
        srsum[tid] = 1.0f / s;
    }
    __syncthreads();

    // softmax probs -> smem overwrite + coalesced logits write
    for (int i = tid; i < BM * E_EXP; i += NT) {
        const int t = i >> 7;
        const int e = i & 127;
        const float p = __expf(Ls[t * LPAD + e] - smax[t]) * srsum[t];
        Ls[t * LPAD + e] = p;
        out[(size_t)(row0 + t) * E_EXP + e] = p;
    }
    __syncthreads();

    // top-8 (strict > keeps lowest index on ties) + renormalize
    if (tid < BM) {
        float* r = Ls + tid * LPAD;
        float vals[TOPK];
        int   idxs[TOPK];
        float s = 0.0f;
        #pragma unroll
        for (int k = 0; k < TOPK; k++) {
            float bv = -1.0f;
            int   bi = 0;
            for (int e = 0; e < E_EXP; e++) {
                float v = r[e];
                if (v > bv) { bv = v; bi = e; }
            }
            r[bi]   = -1.0f;
            vals[k] = bv;
            idxs[k] = bi;
            s += bv;
        }
        const float rs = 1.0f / s;
        const size_t bw = (size_t)T * E_EXP + (size_t)(row0 + tid) * TOPK;
        const size_t bx = (size_t)T * E_EXP + (size_t)T * TOPK + (size_t)(row0 + tid) * TOPK;
        #pragma unroll
        for (int k = 0; k < TOPK; k++) {
            out[bw + k] = vals[k] * rs;
            out[bx + k] = (float)idxs[k];
        }
    }
}

extern "C" void kernel_launch(void* const* d_in, const int* in_sizes, int n_in,
                              void* d_out, int out_size)
{
    const float* X = (const float*)d_in[0];   // hidden_states [T, 2048]
    const float* W = (const float*)d_in[1];   // weight        [128, 2048]
    float* out = (float*)d_out;

    const int T = in_sizes[0] / D_DIM;        // 16384
    static int configured = -1;
    if (configured < 0) {
        cudaFuncSetAttribute(router_mma,
                             cudaFuncAttributeMaxDynamicSharedMemorySize, SMEM_B);
        configured = 1;
    }
    router_mma<<<T / BM, NT, SMEM_B>>>(X, W, out, T);
}